// round 17
// baseline (speedup 1.0000x reference)
#include <cuda_runtime.h>
#include <cstdint>

#define BB 4
#define GG 8
#define NVOX 110592            /* 48*48*48 */
#define NELEM 331776           /* NVOX*3 */
#define KTOP 800
#define VPB 256                /* voxels per block, kernel A */
#define APB (NVOX/VPB)         /* 432 blocks per sample */
#define CAP 16384              /* candidate list capacity per sample */
#define CTH 0xC0000000u        /* ordmap(2.0f): candidate threshold conf > 2.0 */

// ---------------- device scratch (static, zero-init, self-cleaning) ----------
__device__ unsigned g_cand[BB*CAP];
__device__ float    g_pos_sum[BB];
__device__ float    g_reg_sum[BB];
__device__ float    g_neg[BB];
__device__ unsigned g_npos[BB];
__device__ unsigned g_listn[BB];
__device__ unsigned g_negcnt[BB];
__device__ unsigned g_arriveF;

// ---------------- helpers ----------------
__device__ __forceinline__ void fence_rel() { asm volatile("fence.release.gpu;" ::: "memory"); }
__device__ __forceinline__ void fence_acq() { asm volatile("fence.acquire.gpu;" ::: "memory"); }
__device__ __forceinline__ float softplus0(float x) {
    return fmaxf(x, 0.0f) + log1pf(expf(-fabsf(x)));
}
__device__ __forceinline__ float sl1(float x) {
    float ax = fabsf(x);
    return (ax < 1.0f) ? 0.5f * x * x : ax - 0.5f;
}
__device__ __forceinline__ unsigned ordmap(float f) {
    unsigned bb = __float_as_uint(f);
    return (bb & 0x80000000u) ? ~bb : (bb | 0x80000000u);
}
__device__ __forceinline__ float unord(unsigned u) {
    unsigned bb = (u & 0x80000000u) ? (u ^ 0x80000000u) : ~u;
    return __uint_as_float(bb);
}
__device__ __forceinline__ unsigned wscan_incl(unsigned v, int lane) {
#pragma unroll
    for (int o = 1; o < 32; o <<= 1) {
        unsigned t = __shfl_up_sync(0xffffffffu, v, o);
        if (lane >= o) v += t;
    }
    return v;
}
// block-wide inclusive scan for 1024 threads; s_w needs 64 entries
__device__ __forceinline__ unsigned bscan1024(unsigned v, unsigned* s_w, int tid, int lane) {
    unsigned pre = wscan_incl(v, lane);
    if (lane == 31) s_w[tid >> 5] = pre;
    __syncthreads();
    if (tid < 32) {
        unsigned t = s_w[tid];
        unsigned p = wscan_incl(t, tid);
        s_w[32 + tid] = p - t;
    }
    __syncthreads();
    return pre + s_w[32 + (tid >> 5)];
}

// ================= kernel A: staged main pass with geometric fast path =======
// grid (APB, BB), 256 threads, one voxel (3 anchors) per thread, float4 staging
__global__ void __launch_bounds__(256) k_A(const float* __restrict__ pred,
                                           const float* __restrict__ tgt) {
    __shared__ float4 s_stage[960];          // 15360 B: 256 voxels x 15 floats
    __shared__ float s_gxp[GG], s_gxm[GG], s_gyp[GG], s_gym[GG], s_gzp[GG], s_gzm[GG];
    __shared__ float s_gx[GG], s_gy[GG], s_gz[GG], s_gd[GG], s_d3[GG];
    __shared__ int s_mx[48], s_my[48], s_mz[48];
    __shared__ unsigned s_wcnt[8];

    const int b    = blockIdx.y;
    const int tid  = threadIdx.x;
    const int lane = tid & 31;
    const int wid  = tid >> 5;

    if (tid < GG) {
        const float* t = tgt + (b * GG + tid) * 4;
        float gx = t[0], gy = t[1], gz = t[2], gd = t[3];
        float r2 = 0.5f * gd;
        s_gx[tid] = gx; s_gy[tid] = gy; s_gz[tid] = gz; s_gd[tid] = gd;
        s_gxp[tid] = gx + r2; s_gxm[tid] = gx - r2;
        s_gyp[tid] = gy + r2; s_gym[tid] = gy - r2;
        s_gzp[tid] = gz + r2; s_gzm[tid] = gz - r2;
        s_d3[tid] = gd * gd * gd;
    }
    __syncthreads();

    // per-axis GT overlap masks at the largest anchor (r1 = 10)
    if (tid < 144) {
        int axis  = tid / 48;
        int coord = tid - axis * 48;
        float c = (float)(coord * 4 + 2);
        unsigned m = 0u;
#pragma unroll
        for (int g = 0; g < GG; g++) {
            float gp = (axis == 0) ? s_gxp[g] : (axis == 1) ? s_gyp[g] : s_gzp[g];
            float gm = (axis == 0) ? s_gxm[g] : (axis == 1) ? s_gym[g] : s_gzm[g];
            if ((c + 10.0f > gm) && (gp > c - 10.0f)) m |= (1u << g);
        }
        if (axis == 0) s_mx[coord] = (int)m;
        else if (axis == 1) s_my[coord] = (int)m;
        else s_mz[coord] = (int)m;
    }
    __syncthreads();

    // coalesced stage of 256 voxels x 15 floats
    const int vbase = blockIdx.x * VPB;
    const float4* src = (const float4*)(pred + ((size_t)b * NVOX + (size_t)vbase) * 15);
#pragma unroll
    for (int i = 0; i < 4; i++) {
        int idx = tid + i * 256;
        if (idx < 960) s_stage[idx] = src[idx];
    }
    __syncthreads();

    const int vox = vbase + tid;
    const int w = vox % 48; const int t2 = vox / 48;
    const int h = t2 % 48;  const int d = t2 / 48;
    const float* sv = ((const float*)s_stage) + tid * 15;

    bool posA[3], negA[3];
    int bidxA[3];
#pragma unroll
    for (int a = 0; a < 3; a++) { posA[a] = false; negA[a] = true; bidxA[a] = 0; }

    const bool far = ((s_mx[w] & s_my[h] & s_mz[d]) == 0);
    if (!far) {
        const float cx = (float)(w * 4 + 2);
        const float cy = (float)(h * 4 + 2);
        const float cz = (float)(d * 4 + 2);
        const float r1s[3] = {2.5f, 5.0f, 10.0f};
        const float a3s[3] = {125.0f, 1000.0f, 8000.0f};
        float bi[3], bu[3];
#pragma unroll
        for (int a = 0; a < 3; a++) { bi[a] = -1.0f; bu[a] = 1.0f; }
#pragma unroll
        for (int g = 0; g < GG; g++) {
            float xp = s_gxp[g], xm = s_gxm[g];
            float yp = s_gyp[g], ym = s_gym[g];
            float zp = s_gzp[g], zm = s_gzm[g];
            float d3 = s_d3[g];
#pragma unroll
            for (int a = 0; a < 3; a++) {
                float r1 = r1s[a];
                float ix = fminf(cx + r1, xp) - fmaxf(cx - r1, xm); ix = fmaxf(ix, 0.0f);
                float iy = fminf(cy + r1, yp) - fmaxf(cy - r1, ym); iy = fmaxf(iy, 0.0f);
                float iz = fminf(cz + r1, zp) - fmaxf(cz - r1, zm); iz = fmaxf(iz, 0.0f);
                float inter = ix * iy * iz;
                float un = a3s[a] + d3 - inter + 1e-6f;
                if (inter * bu[a] > bi[a] * un) { bi[a] = inter; bu[a] = un; bidxA[a] = g; }
            }
        }
#pragma unroll
        for (int a = 0; a < 3; a++) {
            posA[a] = bi[a] > 0.5f  * bu[a];
            negA[a] = bi[a] < 0.02f * bu[a];
        }
    }

    float lpos = 0.0f, lreg = 0.0f;
    unsigned lnp = 0, lneg = 0;
#pragma unroll
    for (int a = 0; a < 3; a++) {
        const float conf = sv[a * 5];
        const bool neg = negA[a];
        const unsigned u = neg ? ordmap(conf) : 0u;
        lneg += neg ? 1u : 0u;

        // candidate compaction (conf > 2.0): warp-aggregated global push
        const bool cand = neg && (u > CTH);
        unsigned cm = __ballot_sync(0xffffffffu, cand);
        if (cm) {
            int leader = __ffs(cm) - 1;
            unsigned base = 0u;
            if (lane == leader) base = atomicAdd(&g_listn[b], (unsigned)__popc(cm));
            base = __shfl_sync(0xffffffffu, base, leader);
            if (cand) {
                unsigned idx = base + __popc(cm & ((1u << lane) - 1u));
                if (idx < CAP) g_cand[b * CAP + idx] = u;
            }
        }
        if (posA[a]) {
            const float cx = (float)(w * 4 + 2);
            const float cy = (float)(h * 4 + 2);
            const float cz = (float)(d * 4 + 2);
            const float ia = __uint_as_float(0x3E4CCCCDu - ((unsigned)a << 23)); // 0.2/2^a
            lnp++;
            lpos += fmaxf(conf, 0.0f) - conf + log1pf(expf(-fabsf(conf)));
            int g = bidxA[a];
            float tx = (s_gx[g] - cx) * ia;
            float ty = (s_gy[g] - cy) * ia;
            float tz = (s_gz[g] - cz) * ia;
            float td = logf(s_gd[g] * ia);
            lreg += sl1(sv[a*5+1] - tx) + sl1(sv[a*5+2] - ty)
                  + sl1(sv[a*5+3] - tz) + sl1(sv[a*5+4] - td);
        }
    }

    // reductions
#pragma unroll
    for (int o = 16; o; o >>= 1) {
        lpos += __shfl_down_sync(0xffffffffu, lpos, o);
        lreg += __shfl_down_sync(0xffffffffu, lreg, o);
        lnp  += __shfl_down_sync(0xffffffffu, lnp, o);
        lneg += __shfl_down_sync(0xffffffffu, lneg, o);
    }
    if (lane == 0) {
        s_wcnt[wid] = lneg;
        if (lnp) {
            atomicAdd(&g_pos_sum[b], lpos);
            atomicAdd(&g_reg_sum[b], lreg);
            atomicAdd(&g_npos[b], lnp);
        }
    }
    __syncthreads();
    if (tid == 0) {
        unsigned tot = 0;
#pragma unroll
        for (int q = 0; q < 8; q++) tot += s_wcnt[q];
        atomicAdd(&g_negcnt[b], tot);
    }
}

// ================= kernel F: select (list or exact fallback) + finalize ======
// grid (BB), 1024 threads, one block per sample
__global__ void __launch_bounds__(1024) k_F(const float* __restrict__ pred,
                                            const float* __restrict__ tgt,
                                            float* __restrict__ out) {
    __shared__ float s_gxp[GG], s_gxm[GG], s_gyp[GG], s_gym[GG], s_gzp[GG], s_gzm[GG];
    __shared__ unsigned sh[2048];
    __shared__ unsigned s_w[64];
    __shared__ float s_sum;
    __shared__ float s_d3s[GG];
    __shared__ int s_b1, s_b2, s_fin;
    __shared__ unsigned s_k2, s_k3;

    const int b    = blockIdx.x;
    const int tid  = threadIdx.x;
    const int lane = tid & 31;

    const unsigned listn  = g_listn[b];
    const unsigned negcnt = g_negcnt[b];
    const bool valid = (negcnt > KTOP && listn >= KTOP && listn <= CAP);

    if (tid == 0) s_sum = 0.0f;

    if (valid) {
        // ================= list-based exact top-800 =================
        const unsigned n = listn;
        const unsigned nn = (n + 1023u) & ~1023u;
        const unsigned* lst = g_cand + b * CAP;
        __syncthreads();

        // level 1: hist over u>>21 (match-aggregated: bins are concentrated)
        sh[tid] = 0u; sh[tid + 1024] = 0u;
        __syncthreads();
        for (unsigned q = tid; q < nn; q += 1024) {
            const bool ok = (q < n);
            unsigned bin = ok ? (lst[q] >> 21) : (0x10000u + (unsigned)lane);
            unsigned peers = __match_any_sync(0xffffffffu, bin);
            if (ok && (__ffs(peers) - 1 == lane))
                atomicAdd(&sh[bin], (unsigned)__popc(peers));
        }
        __syncthreads();
        {
            const int base = 2047 - 2 * tid;
            unsigned c0 = sh[base], c1 = sh[base - 1];
            unsigned cnt = c0 + c1;
            unsigned pre = bscan1024(cnt, s_w, tid, lane);
            unsigned excl = pre - cnt;
            if (excl < KTOP && pre >= KTOP) {
                if (excl + c0 >= KTOP) { s_b1 = base;     s_k2 = KTOP - excl; }
                else                   { s_b1 = base - 1; s_k2 = KTOP - excl - c0; }
            }
        }
        __syncthreads();
        const int b1 = s_b1;
        const unsigned k2 = s_k2;

        // pass 2
        sh[tid] = 0u; sh[tid + 1024] = 0u;
        __syncthreads();
        float s = 0.0f;
        for (unsigned q = tid; q < n; q += 1024) {
            unsigned u = lst[q];
            int tb = (int)(u >> 21);
            if (tb > b1) s += softplus0(unord(u));
            else if (tb == b1) atomicAdd(&sh[(u >> 10) & 0x7FFu], 1u);
        }
#pragma unroll
        for (int o = 16; o; o >>= 1) s += __shfl_down_sync(0xffffffffu, s, o);
        if (lane == 0 && s != 0.0f) atomicAdd(&s_sum, s);
        __syncthreads();
        {
            const int base = 2047 - 2 * tid;
            unsigned c0 = sh[base], c1 = sh[base - 1];
            unsigned cnt = c0 + c1;
            unsigned pre = bscan1024(cnt, s_w, tid, lane);
            unsigned excl = pre - cnt;
            if (excl < k2 && pre >= k2) {
                if (excl + c0 >= k2) { s_b2 = base;     s_k3 = k2 - excl; }
                else                 { s_b2 = base - 1; s_k3 = k2 - excl - c0; }
            }
        }
        __syncthreads();
        const int b2 = s_b2;
        const unsigned k3 = s_k3;

        // pass 3
        sh[tid] = 0u;
        __syncthreads();
        float s2 = 0.0f;
        for (unsigned q = tid; q < n; q += 1024) {
            unsigned u = lst[q];
            if ((int)(u >> 21) != b1) continue;
            int m = (int)((u >> 10) & 0x7FFu);
            if (m > b2) s2 += softplus0(unord(u));
            else if (m == b2) atomicAdd(&sh[u & 0x3FFu], 1u);
        }
#pragma unroll
        for (int o = 16; o; o >>= 1) s2 += __shfl_down_sync(0xffffffffu, s2, o);
        if (lane == 0 && s2 != 0.0f) atomicAdd(&s_sum, s2);
        __syncthreads();

        // level 3: exact bins, closed form
        {
            const unsigned pref = ((unsigned)b1 << 21) | ((unsigned)b2 << 10);
            const int bin = 1023 - tid;
            unsigned cnt = sh[bin];
            float sp = cnt ? softplus0(unord(pref | (unsigned)bin)) : 0.0f;
            unsigned pre = bscan1024(cnt, s_w, tid, lane);
            unsigned excl = pre - cnt;
            float contrib = 0.0f;
            if (pre <= k3) contrib = (float)cnt * sp;
            else if (excl < k3) contrib = (float)(k3 - excl) * sp;
#pragma unroll
            for (int o = 16; o; o >>= 1) contrib += __shfl_down_sync(0xffffffffu, contrib, o);
            if (lane == 0 && contrib != 0.0f) atomicAdd(&s_sum, contrib);
        }
        __syncthreads();
        if (tid == 0) g_neg[b] = s_sum / (float)KTOP;
    } else {
        // ================= exact fallback (rare) =================
        if (tid < GG) {
            const float* t = tgt + (b * GG + tid) * 4;
            float gx = t[0], gy = t[1], gz = t[2], gd = t[3];
            float r2 = 0.5f * gd;
            s_gxp[tid] = gx + r2; s_gxm[tid] = gx - r2;
            s_gyp[tid] = gy + r2; s_gym[tid] = gy - r2;
            s_gzp[tid] = gz + r2; s_gzm[tid] = gz - r2;
            s_d3s[tid] = gd * gd * gd;
        }
        __syncthreads();

        const unsigned kcnt = (negcnt < KTOP) ? negcnt : KTOP;

        auto calc_u = [&](int e) -> unsigned {
            int vox = e / 3;
            int a   = e - vox * 3;
            int w = vox % 48; int t2 = vox / 48;
            int h = t2 % 48;  int d = t2 / 48;
            float cx = (float)(w * 4 + 2);
            float cy = (float)(h * 4 + 2);
            float cz = (float)(d * 4 + 2);
            float r1 = 2.5f * (float)(1 << a);
            float a3 = 125.0f * (float)(1 << (3 * a));
            float bi = -1.0f, bu = 1.0f;
#pragma unroll
            for (int g = 0; g < GG; g++) {
                float ix = fminf(cx + r1, s_gxp[g]) - fmaxf(cx - r1, s_gxm[g]); ix = fmaxf(ix, 0.0f);
                float iy = fminf(cy + r1, s_gyp[g]) - fmaxf(cy - r1, s_gym[g]); iy = fmaxf(iy, 0.0f);
                float iz = fminf(cz + r1, s_gzp[g]) - fmaxf(cz - r1, s_gzm[g]); iz = fmaxf(iz, 0.0f);
                float inter = ix * iy * iz;
                float un = a3 + s_d3s[g] - inter + 1e-6f;
                if (inter * bu > bi * un) { bi = inter; bu = un; }
            }
            if (!(bi < 0.02f * bu)) return 0u;
            float conf = pred[((size_t)b * NELEM + (size_t)e) * 5];
            return ordmap(conf);
        };

        if (negcnt <= KTOP) {
            float s = 0.0f;
            for (int e = tid; e < NELEM; e += 1024) {
                unsigned u = calc_u(e);
                if (u) s += softplus0(unord(u));
            }
#pragma unroll
            for (int o = 16; o; o >>= 1) s += __shfl_down_sync(0xffffffffu, s, o);
            if (lane == 0 && s != 0.0f) atomicAdd(&s_sum, s);
            __syncthreads();
            if (tid == 0) g_neg[b] = (kcnt > 0) ? s_sum / (float)kcnt : 0.0f;
        } else {
            // level 1 (match-aggregated: generic data can also concentrate)
            sh[tid] = 0u; sh[tid + 1024] = 0u;
            __syncthreads();
            for (int e = tid; e < NELEM; e += 1024) {
                unsigned u = calc_u(e);
                unsigned bin = u ? (u >> 21) : (0x10000u + (unsigned)lane);
                unsigned peers = __match_any_sync(0xffffffffu, bin);
                if (u && (__ffs(peers) - 1 == lane))
                    atomicAdd(&sh[bin], (unsigned)__popc(peers));
            }
            __syncthreads();
            {
                const int base = 2047 - 2 * tid;
                unsigned c0 = sh[base], c1 = sh[base - 1];
                unsigned cnt = c0 + c1;
                unsigned pre = bscan1024(cnt, s_w, tid, lane);
                unsigned excl = pre - cnt;
                if (excl < KTOP && pre >= KTOP) {
                    if (excl + c0 >= KTOP) { s_b1 = base;     s_k2 = KTOP - excl; }
                    else                   { s_b1 = base - 1; s_k2 = KTOP - excl - c0; }
                }
            }
            __syncthreads();
            const int b1 = s_b1; const unsigned k2 = s_k2;
            // pass 2
            sh[tid] = 0u; sh[tid + 1024] = 0u;
            __syncthreads();
            float s = 0.0f;
            for (int e = tid; e < NELEM; e += 1024) {
                unsigned u = calc_u(e);
                if (!u) continue;
                int tb = (int)(u >> 21);
                if (tb > b1) s += softplus0(unord(u));
                else if (tb == b1) atomicAdd(&sh[(u >> 10) & 0x7FFu], 1u);
            }
#pragma unroll
            for (int o = 16; o; o >>= 1) s += __shfl_down_sync(0xffffffffu, s, o);
            if (lane == 0 && s != 0.0f) atomicAdd(&s_sum, s);
            __syncthreads();
            {
                const int base = 2047 - 2 * tid;
                unsigned c0 = sh[base], c1 = sh[base - 1];
                unsigned cnt = c0 + c1;
                unsigned pre = bscan1024(cnt, s_w, tid, lane);
                unsigned excl = pre - cnt;
                if (excl < k2 && pre >= k2) {
                    if (excl + c0 >= k2) { s_b2 = base;     s_k3 = k2 - excl; }
                    else                 { s_b2 = base - 1; s_k3 = k2 - excl - c0; }
                }
            }
            __syncthreads();
            const int b2 = s_b2; const unsigned k3 = s_k3;
            // pass 3
            sh[tid] = 0u;
            __syncthreads();
            float s2 = 0.0f;
            for (int e = tid; e < NELEM; e += 1024) {
                unsigned u = calc_u(e);
                if (!u || (int)(u >> 21) != b1) continue;
                int m = (int)((u >> 10) & 0x7FFu);
                if (m > b2) s2 += softplus0(unord(u));
                else if (m == b2) atomicAdd(&sh[u & 0x3FFu], 1u);
            }
#pragma unroll
            for (int o = 16; o; o >>= 1) s2 += __shfl_down_sync(0xffffffffu, s2, o);
            if (lane == 0 && s2 != 0.0f) atomicAdd(&s_sum, s2);
            __syncthreads();
            {
                const unsigned pref = ((unsigned)b1 << 21) | ((unsigned)b2 << 10);
                const int bin = 1023 - tid;
                unsigned cnt = sh[bin];
                float sp = cnt ? softplus0(unord(pref | (unsigned)bin)) : 0.0f;
                unsigned pre = bscan1024(cnt, s_w, tid, lane);
                unsigned excl = pre - cnt;
                float contrib = 0.0f;
                if (pre <= k3) contrib = (float)cnt * sp;
                else if (excl < k3) contrib = (float)(k3 - excl) * sp;
#pragma unroll
                for (int o = 16; o; o >>= 1) contrib += __shfl_down_sync(0xffffffffu, contrib, o);
                if (lane == 0 && contrib != 0.0f) atomicAdd(&s_sum, contrib);
            }
            __syncthreads();
            if (tid == 0) g_neg[b] = s_sum / (float)KTOP;
        }
    }

    // ---- arrive; last block finalizes + cleans ----
    __syncthreads();
    if (tid == 0) {
        fence_rel();
        s_fin = (atomicAdd(&g_arriveF, 1u) == BB - 1);
    }
    __syncthreads();
    if (s_fin && tid == 0) {
        fence_acq();
        float cls = 0.0f, reg = 0.0f, npsum = 0.0f;
        for (int bb = 0; bb < BB; bb++) {
            float np = (float)g_npos[bb];
            float pl = (np > 0.0f) ? 5.0f * g_pos_sum[bb] / np : 0.0f;
            float rl = (np > 0.0f) ? g_reg_sum[bb] / (4.0f * np) : 0.0f;
            cls += pl + g_neg[bb];
            reg += rl;
            npsum += np;
            g_pos_sum[bb] = 0.0f; g_reg_sum[bb] = 0.0f;
            g_npos[bb] = 0u; g_listn[bb] = 0u; g_negcnt[bb] = 0u;
        }
        g_arriveF = 0u;
        cls *= 0.25f;
        reg *= 0.25f;
        out[0] = cls + 0.5f * reg;
        out[1] = cls;
        out[2] = reg;
        out[3] = npsum;
    }
}

// ---------------- launcher ----------------
extern "C" void kernel_launch(void* const* d_in, const int* in_sizes, int n_in,
                              void* d_out, int out_size) {
    const float* pred = (const float*)d_in[0];   // (4,48,48,48,3,5)
    const float* tgt  = (const float*)d_in[1];   // (4,8,4)
    float* out = (float*)d_out;

    dim3 ga(APB, BB);            // 432 x 4
    k_A<<<ga, 256>>>(pred, tgt);
    k_F<<<BB, 1024>>>(pred, tgt, out);
}